// round 1
// baseline (speedup 1.0000x reference)
#include <cuda_runtime.h>
#include <math.h>

#define NB 131072
#define NC 6
#define D0 100
#define D1 128
#define D2 64
#define D3 32
#define TILE 128
#define NT 256
#define CF_K 0.02f

// dynamic smem layout (floats):
//  As  : 128*100 = 12800   (res tile)
//  Ws  : 12800             (per-layer weights, reused: 100x128 / 128x64 / 64x32)
//  Hs  : 128*128 = 16384   (h1)
//  H2s : 128*64  = 8192    (h2)
//  H3s : 128*33  = 4224    (h3, stride 33 to kill bank conflicts in layer-4 dot)
//  bias: 128
#define SMEM_FLOATS (12800 + 12800 + 16384 + 8192 + 4224 + 128)
#define SMEM_BYTES (SMEM_FLOATS * 4)

__device__ __forceinline__ float sigm(float x) {
    return 1.0f / (1.0f + __expf(-x));
}
__device__ __forceinline__ float silu(float x) {
    return x / (1.0f + __expf(-x));
}

__global__ __launch_bounds__(NT, 1) void mlp_kernel(
    const float* __restrict__ res,
    const float* __restrict__ W1, const float* __restrict__ b1,
    const float* __restrict__ W2, const float* __restrict__ b2,
    const float* __restrict__ W3, const float* __restrict__ b3,
    const float* __restrict__ W4, const float* __restrict__ b4,
    float* __restrict__ raw_out)
{
    extern __shared__ float sm[];
    float* As   = sm;                   // [128][100]
    float* Ws   = As + TILE * D0;       // reused weight buffer
    float* Hs   = Ws + D0 * D1;         // [128][128]
    float* H2s  = Hs + TILE * D1;       // [128][64]
    float* H3s  = H2s + TILE * D2;      // [128][33]
    float* bias = H3s + TILE * 33;      // [128]

    const int c    = blockIdx.y;
    const int tile = blockIdx.x;
    const int tid  = threadIdx.x;
    const int tx   = tid & 15;          // 16 column groups
    const int ty   = tid >> 4;          // 16 row groups

    // ---- load res tile + W1 + b1 ----
    const float* resT = res + (size_t)tile * TILE * D0;
    for (int i = tid; i < TILE * D0; i += NT) As[i] = resT[i];
    const float* w1 = W1 + (size_t)c * D0 * D1;
    for (int i = tid; i < D0 * D1; i += NT) Ws[i] = w1[i];
    if (tid < D1) bias[tid] = b1[c * D1 + tid];
    __syncthreads();

    // ---- layer 1: [128 x 100] @ [100 x 128] ----
    {
        float acc[8][8];
        #pragma unroll
        for (int i = 0; i < 8; i++)
            #pragma unroll
            for (int j = 0; j < 8; j++) acc[i][j] = 0.0f;

        #pragma unroll 4
        for (int k = 0; k < D0; k++) {
            float a[8], bfr[8];
            #pragma unroll
            for (int i = 0; i < 8; i++) a[i] = As[(ty + 16 * i) * D0 + k];
            #pragma unroll
            for (int j = 0; j < 8; j++) bfr[j] = Ws[k * D1 + tx + 16 * j];
            #pragma unroll
            for (int i = 0; i < 8; i++)
                #pragma unroll
                for (int j = 0; j < 8; j++)
                    acc[i][j] = fmaf(a[i], bfr[j], acc[i][j]);
        }
        #pragma unroll
        for (int i = 0; i < 8; i++) {
            int r = ty + 16 * i;
            #pragma unroll
            for (int j = 0; j < 8; j++) {
                int col = tx + 16 * j;
                Hs[r * D1 + col] = silu(acc[i][j] + bias[col]);
            }
        }
    }
    __syncthreads();

    // ---- load W2 + b2 ----
    const float* w2 = W2 + (size_t)c * D1 * D2;
    for (int i = tid; i < D1 * D2; i += NT) Ws[i] = w2[i];
    if (tid < D2) bias[tid] = b2[c * D2 + tid];
    __syncthreads();

    // ---- layer 2: [128 x 128] @ [128 x 64] ----
    {
        float acc[8][4];
        #pragma unroll
        for (int i = 0; i < 8; i++)
            #pragma unroll
            for (int j = 0; j < 4; j++) acc[i][j] = 0.0f;

        #pragma unroll 4
        for (int k = 0; k < D1; k++) {
            float a[8], bfr[4];
            #pragma unroll
            for (int i = 0; i < 8; i++) a[i] = Hs[(ty + 16 * i) * D1 + k];
            #pragma unroll
            for (int j = 0; j < 4; j++) bfr[j] = Ws[k * D2 + tx + 16 * j];
            #pragma unroll
            for (int i = 0; i < 8; i++)
                #pragma unroll
                for (int j = 0; j < 4; j++)
                    acc[i][j] = fmaf(a[i], bfr[j], acc[i][j]);
        }
        #pragma unroll
        for (int i = 0; i < 8; i++) {
            int r = ty + 16 * i;
            #pragma unroll
            for (int j = 0; j < 4; j++) {
                int col = tx + 16 * j;
                H2s[r * D2 + col] = silu(acc[i][j] + bias[col]);
            }
        }
    }
    __syncthreads();

    // ---- load W3 + b3 ----
    const float* w3 = W3 + (size_t)c * D2 * D3;
    for (int i = tid; i < D2 * D3; i += NT) Ws[i] = w3[i];
    if (tid < D3) bias[tid] = b3[c * D3 + tid];
    __syncthreads();

    // ---- layer 3: [128 x 64] @ [64 x 32] ----
    {
        float acc[8][2];
        #pragma unroll
        for (int i = 0; i < 8; i++) { acc[i][0] = 0.0f; acc[i][1] = 0.0f; }

        #pragma unroll 4
        for (int k = 0; k < D2; k++) {
            float a[8], bfr[2];
            #pragma unroll
            for (int i = 0; i < 8; i++) a[i] = H2s[(ty + 16 * i) * D2 + k];
            bfr[0] = Ws[k * D3 + tx];
            bfr[1] = Ws[k * D3 + tx + 16];
            #pragma unroll
            for (int i = 0; i < 8; i++) {
                acc[i][0] = fmaf(a[i], bfr[0], acc[i][0]);
                acc[i][1] = fmaf(a[i], bfr[1], acc[i][1]);
            }
        }
        #pragma unroll
        for (int i = 0; i < 8; i++) {
            int r = ty + 16 * i;
            H3s[r * 33 + tx]      = silu(acc[i][0] + bias[tx]);
            H3s[r * 33 + tx + 16] = silu(acc[i][1] + bias[tx + 16]);
        }
    }
    __syncthreads();

    // ---- layer 4: dot with W4[c], + b4[c] -> raw ----
    if (tid < D3) bias[tid] = W4[c * D3 + tid];
    __syncthreads();

    if (tid < TILE) {
        float s = 0.0f;
        #pragma unroll
        for (int k = 0; k < D3; k++) s = fmaf(H3s[tid * 33 + k], bias[k], s);
        s += b4[c];
        raw_out[((size_t)tile * TILE + tid) * NC + c] = s;
    }
}

__global__ __launch_bounds__(256) void couple_kernel(
    const float* __restrict__ raw, float* __restrict__ act,
    const float* __restrict__ coupling, const float* __restrict__ decay)
{
    __shared__ float M[NC][NC];
    if (threadIdx.x < NC * NC) {
        int cp = threadIdx.x / NC;
        int cc = threadIdx.x % NC;
        M[cp][cc] = decay[cp] * coupling[cp * NC + cc] * CF_K;
    }
    __syncthreads();

    int r = blockIdx.x * blockDim.x + threadIdx.x;
    if (r >= NB) return;

    float rw[NC], a[NC];
    #pragma unroll
    for (int c = 0; c < NC; c++) {
        rw[c] = raw[(size_t)r * NC + c];
        a[c]  = sigm(rw[c]);
    }
    #pragma unroll
    for (int it = 0; it < 5; it++) {
        float d[NC];
        #pragma unroll
        for (int c = 0; c < NC; c++) d[c] = 0.0f;
        #pragma unroll
        for (int cp = 0; cp < NC; cp++)
            #pragma unroll
            for (int cc = 0; cc < NC; cc++)
                d[cc] = fmaf(a[cp], M[cp][cc], d[cc]);
        #pragma unroll
        for (int c = 0; c < NC; c++) a[c] = sigm(rw[c] + d[c]);
    }
    #pragma unroll
    for (int c = 0; c < NC; c++) act[(size_t)r * NC + c] = a[c];
}

extern "C" void kernel_launch(void* const* d_in, const int* in_sizes, int n_in,
                              void* d_out, int out_size)
{
    const float* res      = (const float*)d_in[0];
    const float* W1       = (const float*)d_in[1];
    const float* b1       = (const float*)d_in[2];
    const float* W2       = (const float*)d_in[3];
    const float* b2       = (const float*)d_in[4];
    const float* W3       = (const float*)d_in[5];
    const float* b3       = (const float*)d_in[6];
    const float* W4       = (const float*)d_in[7];
    const float* b4       = (const float*)d_in[8];
    const float* coupling = (const float*)d_in[9];
    const float* decay    = (const float*)d_in[10];

    float* act = (float*)d_out;             // (B, 6)
    float* raw = act + (size_t)NB * NC;     // (B, 6)

    cudaFuncSetAttribute(mlp_kernel, cudaFuncAttributeMaxDynamicSharedMemorySize, SMEM_BYTES);

    dim3 grid(NB / TILE, NC);
    mlp_kernel<<<grid, NT, SMEM_BYTES>>>(res, W1, b1, W2, b2, W3, b3, W4, b4, raw);

    couple_kernel<<<NB / 256, 256>>>(raw, act, coupling, decay);
}

// round 6
// speedup vs baseline: 2.3843x; 2.3843x over previous
#include <cuda_runtime.h>
#include <cstdint>

#define NB 131072
#define NC 6
#define TILE 128
#define NT 256
#define CF_K 0.02f
#define T_PER_CTA 4
#define GRID_X (256 * NC)

// activation strides (uint32 elems) — chosen so (stride mod 32) spreads
// A-fragment loads across all 32 banks
#define SA1 108
#define SH1 132
#define SH2 68

// smem byte offsets
#define OFF_A1  0                        // 128 x 108 f32 (res; H2 overlaid per-stripe)
#define OFF_H1  55296                    // 128 x 132 f32
#define OFF_BW1 122880                   // 13k x 16n x 32lane x uint2  (53248 B)
#define OFF_BW2 176128                   // 16k x 8n  x 32 x uint2      (32768 B)
#define OFF_BW3 208896                   //  8k x 4n  x 32 x uint2      ( 8192 B)
#define OFF_B1  217088
#define OFF_B2  217600
#define OFF_B3  217856
#define OFF_W4  217984
#define SMEM_BYTES 218112

__device__ __forceinline__ uint32_t f2tf32(float x) {
    uint32_t y;
    asm("cvt.rna.tf32.f32 %0, %1;" : "=r"(y) : "f"(x));
    return y;
}

__device__ __forceinline__ void mma_tf32(float* d,
    uint32_t a0, uint32_t a1, uint32_t a2, uint32_t a3,
    uint32_t b0, uint32_t b1)
{
    asm volatile(
        "mma.sync.aligned.m16n8k8.row.col.f32.tf32.tf32.f32 "
        "{%0,%1,%2,%3}, {%4,%5,%6,%7}, {%8,%9}, {%0,%1,%2,%3};"
        : "+f"(d[0]), "+f"(d[1]), "+f"(d[2]), "+f"(d[3])
        : "r"(a0), "r"(a1), "r"(a2), "r"(a3), "r"(b0), "r"(b1));
}

__device__ __forceinline__ float sigm(float x) { return 1.0f / (1.0f + __expf(-x)); }
__device__ __forceinline__ float silu(float x) { return __fdividef(x, 1.0f + __expf(-x)); }

__global__ __launch_bounds__(NT, 1) void mlp_mma_kernel(
    const float* __restrict__ res,
    const float* __restrict__ W1, const float* __restrict__ b1,
    const float* __restrict__ W2, const float* __restrict__ b2,
    const float* __restrict__ W3, const float* __restrict__ b3,
    const float* __restrict__ W4, const float* __restrict__ b4,
    float* __restrict__ raw_out)
{
    extern __shared__ char smb[];
    uint32_t* A1  = (uint32_t*)(smb + OFF_A1);
    uint32_t* H1  = (uint32_t*)(smb + OFF_H1);
    float*    b1s = (float*)(smb + OFF_B1);
    float*    b2s = (float*)(smb + OFF_B2);
    float*    b3s = (float*)(smb + OFF_B3);
    float*    W4s = (float*)(smb + OFF_W4);

    const int bid   = blockIdx.x;
    const int c     = bid % NC;
    const int tbase = bid / NC;

    const int tid  = threadIdx.x;
    const int w    = tid >> 5;
    const int lane = tid & 31;
    const int g    = lane >> 2;     // groupID (row within fragment)
    const int tg   = lane & 3;      // thread-in-group (col within fragment)
    const int m0   = w * 16;        // warp's row stripe

    // ---- one-time: permute weights into per-lane fragment order ----
    {
        const float* w1 = W1 + (size_t)c * 100 * 128;
        for (int idx = tid; idx < 13 * 16 * 32; idx += NT) {
            int kk = idx >> 9, rem = idx & 511;
            int nt = rem >> 5, ln = rem & 31;
            int gg = ln >> 2, tt = ln & 3;
            int k0 = kk * 8 + tt, n = nt * 8 + gg;
            float v0 = (k0     < 100) ? w1[k0 * 128 + n]       : 0.0f;
            float v1 = (k0 + 4 < 100) ? w1[(k0 + 4) * 128 + n] : 0.0f;
            uint2 u; u.x = f2tf32(v0); u.y = f2tf32(v1);
            *(uint2*)(smb + OFF_BW1 + (size_t)idx * 8) = u;
        }
        const float* w2 = W2 + (size_t)c * 128 * 64;
        for (int idx = tid; idx < 16 * 8 * 32; idx += NT) {
            int kk = idx >> 8, rem = idx & 255;
            int nt = rem >> 5, ln = rem & 31;
            int gg = ln >> 2, tt = ln & 3;
            int k0 = kk * 8 + tt, n = nt * 8 + gg;
            uint2 u; u.x = f2tf32(w2[k0 * 64 + n]); u.y = f2tf32(w2[(k0 + 4) * 64 + n]);
            *(uint2*)(smb + OFF_BW2 + (size_t)idx * 8) = u;
        }
        const float* w3 = W3 + (size_t)c * 64 * 32;
        for (int idx = tid; idx < 8 * 4 * 32; idx += NT) {
            int kk = idx >> 7, rem = idx & 127;
            int nt = rem >> 5, ln = rem & 31;
            int gg = ln >> 2, tt = ln & 3;
            int k0 = kk * 8 + tt, n = nt * 8 + gg;
            uint2 u; u.x = f2tf32(w3[k0 * 32 + n]); u.y = f2tf32(w3[(k0 + 4) * 32 + n]);
            *(uint2*)(smb + OFF_BW3 + (size_t)idx * 8) = u;
        }
        if (tid < 128) b1s[tid] = b1[c * 128 + tid];
        if (tid < 64)  b2s[tid] = b2[c * 64 + tid];
        if (tid < 32)  b3s[tid] = b3[c * 32 + tid];
        if (tid < 32)  W4s[tid] = W4[c * 32 + tid];
    }
    const float b4c = b4[c];

    const uint2* BW1 = (const uint2*)(smb + OFF_BW1);
    const uint2* BW2 = (const uint2*)(smb + OFF_BW2);
    const uint2* BW3 = (const uint2*)(smb + OFF_BW3);

    // H2 overlays A1, stripe-locally: row r lives at w*1728 + (r&15)*68
    const int h2base = w * 1728;

    for (int j = 0; j < T_PER_CTA; j++) {
        const size_t row0 = (size_t)(tbase + 256 * j) * TILE;

        __syncthreads();   // all warps done reading H2/A1 from previous tile

        // ---- load res tile (tf32-rounded, K padded 100->104) ----
        {
            const float* rp = res + row0 * 100;
            for (int idx = tid; idx < 128 * 104; idx += NT) {
                int row = idx / 104, k = idx - row * 104;
                float v = (k < 100) ? rp[row * 100 + k] : 0.0f;
                A1[row * SA1 + k] = f2tf32(v);
            }
        }
        __syncthreads();

        // ================= L1: [128x104] @ W1 -> 128x128 =================
        float acc1[16][4];
        #pragma unroll
        for (int nt = 0; nt < 16; nt++)
            #pragma unroll
            for (int q = 0; q < 4; q++) acc1[nt][q] = 0.0f;

        #pragma unroll
        for (int kk = 0; kk < 13; kk++) {
            const int kc = kk * 8;
            uint32_t a0 = A1[(m0 + g) * SA1 + kc + tg];
            uint32_t a1 = A1[(m0 + g + 8) * SA1 + kc + tg];
            uint32_t a2 = A1[(m0 + g) * SA1 + kc + tg + 4];
            uint32_t a3 = A1[(m0 + g + 8) * SA1 + kc + tg + 4];
            const uint2* bp = BW1 + kk * 512 + lane;
            #pragma unroll
            for (int nt = 0; nt < 16; nt++) {
                uint2 b = bp[nt * 32];
                mma_tf32(acc1[nt], a0, a1, a2, a3, b.x, b.y);
            }
        }
        // epi1 -> H1 (own stripe only; no sync needed)
        #pragma unroll
        for (int nt = 0; nt < 16; nt++) {
            int col = nt * 8 + 2 * tg;
            float ba = b1s[col], bb = b1s[col + 1];
            uint2 u0, u1;
            u0.x = f2tf32(silu(acc1[nt][0] + ba));
            u0.y = f2tf32(silu(acc1[nt][1] + bb));
            u1.x = f2tf32(silu(acc1[nt][2] + ba));
            u1.y = f2tf32(silu(acc1[nt][3] + bb));
            *(uint2*)&H1[(m0 + g) * SH1 + col]     = u0;
            *(uint2*)&H1[(m0 + g + 8) * SH1 + col] = u1;
        }

        // ================= L2: [128x128] @ W2 -> 128x64 =================
        float acc2[8][4];
        #pragma unroll
        for (int nt = 0; nt < 8; nt++)
            #pragma unroll
            for (int q = 0; q < 4; q++) acc2[nt][q] = 0.0f;

        #pragma unroll
        for (int kk = 0; kk < 16; kk++) {
            const int kc = kk * 8;
            uint32_t a0 = H1[(m0 + g) * SH1 + kc + tg];
            uint32_t a1 = H1[(m0 + g + 8) * SH1 + kc + tg];
            uint32_t a2 = H1[(m0 + g) * SH1 + kc + tg + 4];
            uint32_t a3 = H1[(m0 + g + 8) * SH1 + kc + tg + 4];
            const uint2* bp = BW2 + kk * 256 + lane;
            #pragma unroll
            for (int nt = 0; nt < 8; nt++) {
                uint2 b = bp[nt * 32];
                mma_tf32(acc2[nt], a0, a1, a2, a3, b.x, b.y);
            }
        }
        // epi2 -> H2 (overlaid in own A1 stripe; own stripe only)
        #pragma unroll
        for (int nt = 0; nt < 8; nt++) {
            int col = nt * 8 + 2 * tg;
            float ba = b2s[col], bb = b2s[col + 1];
            uint2 u0, u1;
            u0.x = f2tf32(silu(acc2[nt][0] + ba));
            u0.y = f2tf32(silu(acc2[nt][1] + bb));
            u1.x = f2tf32(silu(acc2[nt][2] + ba));
            u1.y = f2tf32(silu(acc2[nt][3] + bb));
            *(uint2*)&A1[h2base + g * SH2 + col]       = u0;
            *(uint2*)&A1[h2base + (g + 8) * SH2 + col] = u1;
        }

        // ================= L3: [128x64] @ W3 -> 128x32 =================
        float acc3[4][4];
        #pragma unroll
        for (int nt = 0; nt < 4; nt++)
            #pragma unroll
            for (int q = 0; q < 4; q++) acc3[nt][q] = 0.0f;

        #pragma unroll
        for (int kk = 0; kk < 8; kk++) {
            const int kc = kk * 8;
            uint32_t a0 = A1[h2base + g * SH2 + kc + tg];
            uint32_t a1 = A1[h2base + (g + 8) * SH2 + kc + tg];
            uint32_t a2 = A1[h2base + g * SH2 + kc + tg + 4];
            uint32_t a3 = A1[h2base + (g + 8) * SH2 + kc + tg + 4];
            const uint2* bp = BW3 + kk * 128 + lane;
            #pragma unroll
            for (int nt = 0; nt < 4; nt++) {
                uint2 b = bp[nt * 32];
                mma_tf32(acc3[nt], a0, a1, a2, a3, b.x, b.y);
            }
        }

        // ---- epi3: raw = silu(D3 + b3) . W4 + b4 (quarter-warp reduce) ----
        {
            float s0 = 0.0f, s1 = 0.0f;
            #pragma unroll
            for (int nt = 0; nt < 4; nt++) {
                int col = nt * 8 + 2 * tg;
                float ba = b3s[col], bb = b3s[col + 1];
                float wa = W4s[col], wb = W4s[col + 1];
                s0 = fmaf(silu(acc3[nt][0] + ba), wa, s0);
                s0 = fmaf(silu(acc3[nt][1] + bb), wb, s0);
                s1 = fmaf(silu(acc3[nt][2] + ba), wa, s1);
                s1 = fmaf(silu(acc3[nt][3] + bb), wb, s1);
            }
            s0 += __shfl_xor_sync(0xffffffff, s0, 1);
            s0 += __shfl_xor_sync(0xffffffff, s0, 2);
            s1 += __shfl_xor_sync(0xffffffff, s1, 1);
            s1 += __shfl_xor_sync(0xffffffff, s1, 2);
            if (tg == 0) {
                raw_out[(row0 + m0 + g) * NC + c]     = s0 + b4c;
                raw_out[(row0 + m0 + g + 8) * NC + c] = s1 + b4c;
            }
        }
    }
}

__global__ __launch_bounds__(256) void couple_kernel(
    const float* __restrict__ raw, float* __restrict__ act,
    const float* __restrict__ coupling, const float* __restrict__ decay)
{
    __shared__ float M[NC][NC];
    if (threadIdx.x < NC * NC) {
        int cp = threadIdx.x / NC;
        int cc = threadIdx.x % NC;
        M[cp][cc] = decay[cp] * coupling[cp * NC + cc] * CF_K;
    }
    __syncthreads();

    int r = blockIdx.x * blockDim.x + threadIdx.x;
    if (r >= NB) return;

    float rw[NC], a[NC];
    #pragma unroll
    for (int c = 0; c < NC; c++) {
        rw[c] = raw[(size_t)r * NC + c];
        a[c]  = sigm(rw[c]);
    }
    #pragma unroll
    for (int it = 0; it < 5; it++) {
        float d[NC];
        #pragma unroll
        for (int c = 0; c < NC; c++) d[c] = 0.0f;
        #pragma unroll
        for (int cp = 0; cp < NC; cp++)
            #pragma unroll
            for (int cc = 0; cc < NC; cc++)
                d[cc] = fmaf(a[cp], M[cp][cc], d[cc]);
        #pragma unroll
        for (int c = 0; c < NC; c++) a[c] = sigm(rw[c] + d[c]);
    }
    #pragma unroll
    for (int c = 0; c < NC; c++) act[(size_t)r * NC + c] = a[c];
}

extern "C" void kernel_launch(void* const* d_in, const int* in_sizes, int n_in,
                              void* d_out, int out_size)
{
    (void)in_sizes; (void)n_in; (void)out_size;
    const float* res      = (const float*)d_in[0];
    const float* W1       = (const float*)d_in[1];
    const float* b1       = (const float*)d_in[2];
    const float* W2       = (const float*)d_in[3];
    const float* b2       = (const float*)d_in[4];
    const float* W3       = (const float*)d_in[5];
    const float* b3       = (const float*)d_in[6];
    const float* W4       = (const float*)d_in[7];
    const float* b4       = (const float*)d_in[8];
    const float* coupling = (const float*)d_in[9];
    const float* decay    = (const float*)d_in[10];

    float* act = (float*)d_out;             // (B, 6)
    float* raw = act + (size_t)NB * NC;     // (B, 6)

    cudaFuncSetAttribute(mlp_mma_kernel, cudaFuncAttributeMaxDynamicSharedMemorySize, SMEM_BYTES);

    mlp_mma_kernel<<<GRID_X, NT, SMEM_BYTES>>>(res, W1, b1, W2, b2, W3, b3, W4, b4, raw);
    couple_kernel<<<NB / 256, 256>>>(raw, act, coupling, decay);
}

// round 8
// speedup vs baseline: 3.0481x; 1.2784x over previous
#include <cuda_runtime.h>
#include <cstdint>

#define NB 131072
#define NC 6
#define TILE 128
#define NT 512
#define CF_K 0.02f
#define T_PER_CTA 4
#define GRID_X (256 * NC)

// activation strides (uint32 elems)
#define SA1 108
#define SH1 132
#define SH2 68

// smem byte offsets
#define OFF_A1  0                        // 128 x 108 f32 (res; H2 overlaid per-stripe)
#define OFF_H1  55296                    // 128 x 132 f32
#define OFF_BW1 122880                   // 13k x 16n x 32lane x uint2  (53248 B)
#define OFF_BW2 176128                   // 16k x 8n  x 32 x uint2      (32768 B)
#define OFF_BW3 208896                   //  8k x 4n  x 32 x uint2      ( 8192 B)
#define OFF_B1  217088
#define OFF_B2  217600
#define OFF_B3  217856
#define OFF_W4  217984
#define OFF_P   218112                   // 128 x 2 f32 partials (1024 B)
#define SMEM_BYTES 219136

__device__ __forceinline__ uint32_t f2tf32(float x) {
    uint32_t y;
    asm("cvt.rna.tf32.f32 %0, %1;" : "=r"(y) : "f"(x));
    return y;
}

__device__ __forceinline__ void mma_tf32(float* d,
    uint32_t a0, uint32_t a1, uint32_t a2, uint32_t a3,
    uint32_t b0, uint32_t b1)
{
    asm volatile(
        "mma.sync.aligned.m16n8k8.row.col.f32.tf32.tf32.f32 "
        "{%0,%1,%2,%3}, {%4,%5,%6,%7}, {%8,%9}, {%0,%1,%2,%3};"
        : "+f"(d[0]), "+f"(d[1]), "+f"(d[2]), "+f"(d[3])
        : "r"(a0), "r"(a1), "r"(a2), "r"(a3), "r"(b0), "r"(b1));
}

__device__ __forceinline__ float sigm(float x) { return 1.0f / (1.0f + __expf(-x)); }
// silu(x) = x*sigmoid(x) = 0.5x + 0.5x*tanh(x/2)  (1 MUFU instead of 2)
__device__ __forceinline__ float silu(float x) {
    float t;
    asm("tanh.approx.f32 %0, %1;" : "=f"(t) : "f"(0.5f * x));
    float hx = 0.5f * x;
    return fmaf(hx, t, hx);
}

__global__ __launch_bounds__(NT, 1) void mlp_mma_kernel(
    const float* __restrict__ res,
    const float* __restrict__ W1, const float* __restrict__ b1,
    const float* __restrict__ W2, const float* __restrict__ b2,
    const float* __restrict__ W3, const float* __restrict__ b3,
    const float* __restrict__ W4, const float* __restrict__ b4,
    float* __restrict__ raw_out)
{
    extern __shared__ char smb[];
    uint32_t* A1  = (uint32_t*)(smb + OFF_A1);
    uint32_t* H1  = (uint32_t*)(smb + OFF_H1);
    float*    b1s = (float*)(smb + OFF_B1);
    float*    b2s = (float*)(smb + OFF_B2);
    float*    b3s = (float*)(smb + OFF_B3);
    float*    W4s = (float*)(smb + OFF_W4);
    float*    P2  = (float*)(smb + OFF_P);    // [128][2]

    const int bid   = blockIdx.x;
    const int c     = bid % NC;
    const int tbase = bid / NC;

    const int tid   = threadIdx.x;
    const int w     = tid >> 5;
    const int lane  = tid & 31;
    const int g     = lane >> 2;
    const int tg    = lane & 3;
    const int mwarp = w >> 1;        // 0..7: row stripe
    const int half  = w & 1;         // 0..1: N half
    const int m0    = mwarp * 16;

    // ---- one-time: permute weights into per-lane fragment order ----
    {
        const float* w1 = W1 + (size_t)c * 100 * 128;
        for (int idx = tid; idx < 13 * 16 * 32; idx += NT) {
            int kk = idx >> 9, rem = idx & 511;
            int nt = rem >> 5, ln = rem & 31;
            int gg = ln >> 2, tt = ln & 3;
            int k0 = kk * 8 + tt, n = nt * 8 + gg;
            float v0 = (k0     < 100) ? w1[k0 * 128 + n]       : 0.0f;
            float v1 = (k0 + 4 < 100) ? w1[(k0 + 4) * 128 + n] : 0.0f;
            uint2 u; u.x = f2tf32(v0); u.y = f2tf32(v1);
            *(uint2*)(smb + OFF_BW1 + (size_t)idx * 8) = u;
        }
        const float* w2 = W2 + (size_t)c * 128 * 64;
        for (int idx = tid; idx < 16 * 8 * 32; idx += NT) {
            int kk = idx >> 8, rem = idx & 255;
            int nt = rem >> 5, ln = rem & 31;
            int gg = ln >> 2, tt = ln & 3;
            int k0 = kk * 8 + tt, n = nt * 8 + gg;
            uint2 u; u.x = f2tf32(w2[k0 * 64 + n]); u.y = f2tf32(w2[(k0 + 4) * 64 + n]);
            *(uint2*)(smb + OFF_BW2 + (size_t)idx * 8) = u;
        }
        const float* w3 = W3 + (size_t)c * 64 * 32;
        for (int idx = tid; idx < 8 * 4 * 32; idx += NT) {
            int kk = idx >> 7, rem = idx & 127;
            int nt = rem >> 5, ln = rem & 31;
            int gg = ln >> 2, tt = ln & 3;
            int k0 = kk * 8 + tt, n = nt * 8 + gg;
            uint2 u; u.x = f2tf32(w3[k0 * 32 + n]); u.y = f2tf32(w3[(k0 + 4) * 32 + n]);
            *(uint2*)(smb + OFF_BW3 + (size_t)idx * 8) = u;
        }
        if (tid < 128) b1s[tid] = b1[c * 128 + tid];
        if (tid < 64)  b2s[tid] = b2[c * 64 + tid];
        if (tid < 32)  b3s[tid] = b3[c * 32 + tid];
        if (tid < 32)  W4s[tid] = W4[c * 32 + tid];
    }
    const float b4c = b4[c];

    const uint2* BW1 = (const uint2*)(smb + OFF_BW1);
    const uint2* BW2 = (const uint2*)(smb + OFF_BW2);
    const uint2* BW3 = (const uint2*)(smb + OFF_BW3);

    // H2 overlays A1, stripe-locally per mwarp
    const int h2base = mwarp * 1728;

    for (int j = 0; j < T_PER_CTA; j++) {
        const size_t row0 = (size_t)(tbase + 256 * j) * TILE;

        __syncthreads();   // everyone done reading A1/P2 from previous tile

        // ---- load res tile (tf32-rounded, K padded 100->104) ----
        {
            const float* rp = res + row0 * 100;
            for (int idx = tid; idx < 128 * 104; idx += NT) {
                int row = idx / 104, k = idx - row * 104;
                float v = (k < 100) ? rp[row * 100 + k] : 0.0f;
                A1[row * SA1 + k] = f2tf32(v);
            }
        }
        __syncthreads();

        // ================= L1: [128x104] @ W1 -> 128x128 (8 nt per warp) =====
        float acc1[8][4];
        #pragma unroll
        for (int l = 0; l < 8; l++)
            #pragma unroll
            for (int q = 0; q < 4; q++) acc1[l][q] = 0.0f;

        #pragma unroll
        for (int kk = 0; kk < 13; kk++) {
            const int kc = kk * 8;
            uint32_t a0 = A1[(m0 + g) * SA1 + kc + tg];
            uint32_t a1 = A1[(m0 + g + 8) * SA1 + kc + tg];
            uint32_t a2 = A1[(m0 + g) * SA1 + kc + tg + 4];
            uint32_t a3 = A1[(m0 + g + 8) * SA1 + kc + tg + 4];
            const uint2* bp = BW1 + kk * 512 + (half * 8) * 32 + lane;
            #pragma unroll
            for (int l = 0; l < 8; l++) {
                uint2 b = bp[l * 32];
                mma_tf32(acc1[l], a0, a1, a2, a3, b.x, b.y);
            }
        }
        // epi1 -> H1 (own stripe, own col-half)
        #pragma unroll
        for (int l = 0; l < 8; l++) {
            int col = (half * 8 + l) * 8 + 2 * tg;
            float ba = b1s[col], bb = b1s[col + 1];
            uint2 u0, u1;
            u0.x = f2tf32(silu(acc1[l][0] + ba));
            u0.y = f2tf32(silu(acc1[l][1] + bb));
            u1.x = f2tf32(silu(acc1[l][2] + ba));
            u1.y = f2tf32(silu(acc1[l][3] + bb));
            *(uint2*)&H1[(m0 + g) * SH1 + col]     = u0;
            *(uint2*)&H1[(m0 + g + 8) * SH1 + col] = u1;
        }
        __syncthreads();   // both halves of each stripe complete

        // ================= L2: [128x128] @ W2 -> 128x64 (4 nt per warp) ======
        float acc2[4][4];
        #pragma unroll
        for (int l = 0; l < 4; l++)
            #pragma unroll
            for (int q = 0; q < 4; q++) acc2[l][q] = 0.0f;

        #pragma unroll
        for (int kk = 0; kk < 16; kk++) {
            const int kc = kk * 8;
            uint32_t a0 = H1[(m0 + g) * SH1 + kc + tg];
            uint32_t a1 = H1[(m0 + g + 8) * SH1 + kc + tg];
            uint32_t a2 = H1[(m0 + g) * SH1 + kc + tg + 4];
            uint32_t a3 = H1[(m0 + g + 8) * SH1 + kc + tg + 4];
            const uint2* bp = BW2 + kk * 256 + (half * 4) * 32 + lane;
            #pragma unroll
            for (int l = 0; l < 4; l++) {
                uint2 b = bp[l * 32];
                mma_tf32(acc2[l], a0, a1, a2, a3, b.x, b.y);
            }
        }
        // epi2 -> H2 (overlaid in own stripe of A1, own col-half)
        #pragma unroll
        for (int l = 0; l < 4; l++) {
            int col = (half * 4 + l) * 8 + 2 * tg;
            float ba = b2s[col], bb = b2s[col + 1];
            uint2 u0, u1;
            u0.x = f2tf32(silu(acc2[l][0] + ba));
            u0.y = f2tf32(silu(acc2[l][1] + bb));
            u1.x = f2tf32(silu(acc2[l][2] + ba));
            u1.y = f2tf32(silu(acc2[l][3] + bb));
            *(uint2*)&A1[h2base + g * SH2 + col]       = u0;
            *(uint2*)&A1[h2base + (g + 8) * SH2 + col] = u1;
        }
        __syncthreads();

        // ================= L3: [128x64] @ W3 -> 128x32 (2 nt per warp) =======
        float acc3[2][4];
        #pragma unroll
        for (int l = 0; l < 2; l++)
            #pragma unroll
            for (int q = 0; q < 4; q++) acc3[l][q] = 0.0f;

        #pragma unroll
        for (int kk = 0; kk < 8; kk++) {
            const int kc = kk * 8;
            uint32_t a0 = A1[h2base + g * SH2 + kc + tg];
            uint32_t a1 = A1[h2base + (g + 8) * SH2 + kc + tg];
            uint32_t a2 = A1[h2base + g * SH2 + kc + tg + 4];
            uint32_t a3 = A1[h2base + (g + 8) * SH2 + kc + tg + 4];
            const uint2* bp = BW3 + kk * 128 + (half * 2) * 32 + lane;
            #pragma unroll
            for (int l = 0; l < 2; l++) {
                uint2 b = bp[l * 32];
                mma_tf32(acc3[l], a0, a1, a2, a3, b.x, b.y);
            }
        }

        // ---- epi3: partial dot over this warp's 16 cols ----
        {
            float s0 = 0.0f, s1 = 0.0f;
            #pragma unroll
            for (int l = 0; l < 2; l++) {
                int col = (half * 2 + l) * 8 + 2 * tg;
                float ba = b3s[col], bb = b3s[col + 1];
                float wa = W4s[col], wb = W4s[col + 1];
                s0 = fmaf(silu(acc3[l][0] + ba), wa, s0);
                s0 = fmaf(silu(acc3[l][1] + bb), wb, s0);
                s1 = fmaf(silu(acc3[l][2] + ba), wa, s1);
                s1 = fmaf(silu(acc3[l][3] + bb), wb, s1);
            }
            s0 += __shfl_xor_sync(0xffffffff, s0, 1);
            s0 += __shfl_xor_sync(0xffffffff, s0, 2);
            s1 += __shfl_xor_sync(0xffffffff, s1, 1);
            s1 += __shfl_xor_sync(0xffffffff, s1, 2);
            if (tg == 0) {
                P2[(m0 + g) * 2 + half]     = s0;
                P2[(m0 + g + 8) * 2 + half] = s1;
            }
        }
        __syncthreads();
        if (tid < 128) {
            raw_out[(row0 + tid) * NC + c] = P2[tid * 2] + P2[tid * 2 + 1] + b4c;
        }
    }
}

__global__ __launch_bounds__(256) void couple_kernel(
    const float* __restrict__ raw, float* __restrict__ act,
    const float* __restrict__ coupling, const float* __restrict__ decay)
{
    __shared__ float M[NC][NC];
    if (threadIdx.x < NC * NC) {
        int cp = threadIdx.x / NC;
        int cc = threadIdx.x % NC;
        M[cp][cc] = decay[cp] * coupling[cp * NC + cc] * CF_K;
    }
    __syncthreads();

    int r = blockIdx.x * blockDim.x + threadIdx.x;
    if (r >= NB) return;

    float rw[NC], a[NC];
    #pragma unroll
    for (int c = 0; c < NC; c++) {
        rw[c] = raw[(size_t)r * NC + c];
        a[c]  = sigm(rw[c]);
    }
    #pragma unroll
    for (int it = 0; it < 5; it++) {
        float d[NC];
        #pragma unroll
        for (int c = 0; c < NC; c++) d[c] = 0.0f;
        #pragma unroll
        for (int cp = 0; cp < NC; cp++)
            #pragma unroll
            for (int cc = 0; cc < NC; cc++)
                d[cc] = fmaf(a[cp], M[cp][cc], d[cc]);
        #pragma unroll
        for (int c = 0; c < NC; c++) a[c] = sigm(rw[c] + d[c]);
    }
    #pragma unroll
    for (int c = 0; c < NC; c++) act[(size_t)r * NC + c] = a[c];
}

extern "C" void kernel_launch(void* const* d_in, const int* in_sizes, int n_in,
                              void* d_out, int out_size)
{
    (void)in_sizes; (void)n_in; (void)out_size;
    const float* res      = (const float*)d_in[0];
    const float* W1       = (const float*)d_in[1];
    const float* b1       = (const float*)d_in[2];
    const float* W2       = (const float*)d_in[3];
    const float* b2       = (const float*)d_in[4];
    const float* W3       = (const float*)d_in[5];
    const float* b3       = (const float*)d_in[6];
    const float* W4       = (const float*)d_in[7];
    const float* b4       = (const float*)d_in[8];
    const float* coupling = (const float*)d_in[9];
    const float* decay    = (const float*)d_in[10];

    float* act = (float*)d_out;             // (B, 6)
    float* raw = act + (size_t)NB * NC;     // (B, 6)

    cudaFuncSetAttribute(mlp_mma_kernel, cudaFuncAttributeMaxDynamicSharedMemorySize, SMEM_BYTES);

    mlp_mma_kernel<<<GRID_X, NT, SMEM_BYTES>>>(res, W1, b1, W2, b2, W3, b3, W4, b4, raw);
    couple_kernel<<<NB / 256, 256>>>(raw, act, coupling, decay);
}

// round 11
// speedup vs baseline: 3.6127x; 1.1852x over previous
#include <cuda_runtime.h>
#include <cstdint>

#define NB 131072
#define NC 6
#define TILE 128
#define NT 1024
#define CF_K 0.02f
#define T_PER_CTA 4
#define GRID_X (256 * NC)

// activation strides (uint32 elems)
#define SA1 108
#define SH1 132
#define SH2 68

// smem byte offsets
#define OFF_A1  0                        // 128 x 108 f32 (res; H2 overlaid per-stripe)
#define OFF_H1  55296                    // 128 x 132 f32
#define OFF_BW1 122880                   // 13k x 16n x 32lane x uint2  (53248 B)
#define OFF_BW2 176128                   // 16k x 8n  x 32 x uint2      (32768 B)
#define OFF_BW3 208896                   //  8k x 4n  x 32 x uint2      ( 8192 B)
#define OFF_B1  217088
#define OFF_B2  217600
#define OFF_B3  217856
#define OFF_W4  217984
#define OFF_P   218112                   // 128 x 4 f32 partials (2048 B)
#define SMEM_BYTES 220160

__device__ __forceinline__ uint32_t f2tf32(float x) {
    uint32_t y;
    asm("cvt.rna.tf32.f32 %0, %1;" : "=r"(y) : "f"(x));
    return y;
}

__device__ __forceinline__ void mma_tf32(float* d,
    uint32_t a0, uint32_t a1, uint32_t a2, uint32_t a3,
    uint32_t b0, uint32_t b1)
{
    asm volatile(
        "mma.sync.aligned.m16n8k8.row.col.f32.tf32.tf32.f32 "
        "{%0,%1,%2,%3}, {%4,%5,%6,%7}, {%8,%9}, {%0,%1,%2,%3};"
        : "+f"(d[0]), "+f"(d[1]), "+f"(d[2]), "+f"(d[3])
        : "r"(a0), "r"(a1), "r"(a2), "r"(a3), "r"(b0), "r"(b1));
}

__device__ __forceinline__ float sigm(float x) { return 1.0f / (1.0f + __expf(-x)); }
// silu(x) = 0.5x + 0.5x*tanh(x/2)  (1 MUFU)
__device__ __forceinline__ float silu(float x) {
    float t;
    asm("tanh.approx.f32 %0, %1;" : "=f"(t) : "f"(0.5f * x));
    float hx = 0.5f * x;
    return fmaf(hx, t, hx);
}

// per-stripe barrier: 4 warps (128 threads), HW barrier id = stripe+1
#define BAR_STRIPE(id) asm volatile("bar.sync %0, 128;" :: "r"(id) : "memory")

__global__ __launch_bounds__(NT, 1) void mlp_mma_kernel(
    const float* __restrict__ res,
    const float* __restrict__ W1, const float* __restrict__ b1,
    const float* __restrict__ W2, const float* __restrict__ b2,
    const float* __restrict__ W3, const float* __restrict__ b3,
    const float* __restrict__ W4, const float* __restrict__ b4,
    float* __restrict__ raw_out)
{
    extern __shared__ char smb[];
    uint32_t* A1  = (uint32_t*)(smb + OFF_A1);
    uint32_t* H1  = (uint32_t*)(smb + OFF_H1);
    float*    b1s = (float*)(smb + OFF_B1);
    float*    b2s = (float*)(smb + OFF_B2);
    float*    b3s = (float*)(smb + OFF_B3);
    float*    W4s = (float*)(smb + OFF_W4);
    float*    P4  = (float*)(smb + OFF_P);    // [128][4]

    const int bid   = blockIdx.x;
    const int c     = bid % NC;
    const int tbase = bid / NC;

    const int tid    = threadIdx.x;
    const int w      = tid >> 5;
    const int lane   = tid & 31;
    const int g      = lane >> 2;
    const int tg     = lane & 3;
    const int stripe = w >> 2;       // 0..7: 16-row stripe
    const int q      = w & 3;        // 0..3: N quarter
    const int m0     = stripe * 16;
    const int barid  = stripe + 1;
    const int sg_tid = tid & 127;    // thread id within stripe group

    // ---- one-time: permute weights into per-lane fragment order ----
    {
        const float* w1 = W1 + (size_t)c * 100 * 128;
        for (int idx = tid; idx < 13 * 16 * 32; idx += NT) {
            int kk = idx >> 9, rem = idx & 511;
            int nt = rem >> 5, ln = rem & 31;
            int gg = ln >> 2, tt = ln & 3;
            int k0 = kk * 8 + tt, n = nt * 8 + gg;
            float v0 = (k0     < 100) ? w1[k0 * 128 + n]       : 0.0f;
            float v1 = (k0 + 4 < 100) ? w1[(k0 + 4) * 128 + n] : 0.0f;
            uint2 u; u.x = f2tf32(v0); u.y = f2tf32(v1);
            *(uint2*)(smb + OFF_BW1 + (size_t)idx * 8) = u;
        }
        const float* w2 = W2 + (size_t)c * 128 * 64;
        for (int idx = tid; idx < 16 * 8 * 32; idx += NT) {
            int kk = idx >> 8, rem = idx & 255;
            int nt = rem >> 5, ln = rem & 31;
            int gg = ln >> 2, tt = ln & 3;
            int k0 = kk * 8 + tt, n = nt * 8 + gg;
            uint2 u; u.x = f2tf32(w2[k0 * 64 + n]); u.y = f2tf32(w2[(k0 + 4) * 64 + n]);
            *(uint2*)(smb + OFF_BW2 + (size_t)idx * 8) = u;
        }
        const float* w3 = W3 + (size_t)c * 64 * 32;
        for (int idx = tid; idx < 8 * 4 * 32; idx += NT) {
            int kk = idx >> 7, rem = idx & 127;
            int nt = rem >> 5, ln = rem & 31;
            int gg = ln >> 2, tt = ln & 3;
            int k0 = kk * 8 + tt, n = nt * 8 + gg;
            uint2 u; u.x = f2tf32(w3[k0 * 32 + n]); u.y = f2tf32(w3[(k0 + 4) * 32 + n]);
            *(uint2*)(smb + OFF_BW3 + (size_t)idx * 8) = u;
        }
        if (tid < 128) b1s[tid] = b1[c * 128 + tid];
        if (tid < 64)  b2s[tid] = b2[c * 64 + tid];
        if (tid < 32)  b3s[tid] = b3[c * 32 + tid];
        if (tid < 32)  W4s[tid] = W4[c * 32 + tid];
    }
    const float b4c = b4[c];
    __syncthreads();

    const uint2* BW1 = (const uint2*)(smb + OFF_BW1);
    const uint2* BW2 = (const uint2*)(smb + OFF_BW2);
    const uint2* BW3 = (const uint2*)(smb + OFF_BW3);

    // H2 overlays A1, stripe-locally
    const int h2base = stripe * 1728;

    for (int j = 0; j < T_PER_CTA; j++) {
        const size_t row0 = (size_t)(tbase + 256 * j) * TILE;

        // ---- load this stripe's 16 res rows (tf32, K padded 100->104) ----
        {
            const float* rp = res + (row0 + m0) * 100;
            #pragma unroll
            for (int i = 0; i < 13; i++) {
                int idx = sg_tid + i * 128;        // 0..1663
                int rr = idx / 104, k = idx - rr * 104;
                float v = (k < 100) ? rp[rr * 100 + k] : 0.0f;
                A1[(m0 + rr) * SA1 + k] = f2tf32(v);
            }
        }
        BAR_STRIPE(barid);

        // ================= L1: stripe [16x104] @ W1 -> 16x32 (4 nt) =========
        float acc1[4][4];
        #pragma unroll
        for (int l = 0; l < 4; l++)
            #pragma unroll
            for (int p = 0; p < 4; p++) acc1[l][p] = 0.0f;

        #pragma unroll
        for (int kk = 0; kk < 13; kk++) {
            const int kc = kk * 8;
            uint32_t a0 = A1[(m0 + g) * SA1 + kc + tg];
            uint32_t a1 = A1[(m0 + g + 8) * SA1 + kc + tg];
            uint32_t a2 = A1[(m0 + g) * SA1 + kc + tg + 4];
            uint32_t a3 = A1[(m0 + g + 8) * SA1 + kc + tg + 4];
            const uint2* bp = BW1 + kk * 512 + (q * 4) * 32 + lane;
            #pragma unroll
            for (int l = 0; l < 4; l++) {
                uint2 b = bp[l * 32];
                mma_tf32(acc1[l], a0, a1, a2, a3, b.x, b.y);
            }
        }
        #pragma unroll
        for (int l = 0; l < 4; l++) {
            int col = (q * 4 + l) * 8 + 2 * tg;
            float ba = b1s[col], bb = b1s[col + 1];
            uint2 u0, u1;
            u0.x = f2tf32(silu(acc1[l][0] + ba));
            u0.y = f2tf32(silu(acc1[l][1] + bb));
            u1.x = f2tf32(silu(acc1[l][2] + ba));
            u1.y = f2tf32(silu(acc1[l][3] + bb));
            *(uint2*)&H1[(m0 + g) * SH1 + col]     = u0;
            *(uint2*)&H1[(m0 + g + 8) * SH1 + col] = u1;
        }
        BAR_STRIPE(barid);

        // ================= L2: [16x128] @ W2 -> 16x16 (2 nt) ================
        float acc2[2][4];
        #pragma unroll
        for (int l = 0; l < 2; l++)
            #pragma unroll
            for (int p = 0; p < 4; p++) acc2[l][p] = 0.0f;

        #pragma unroll
        for (int kk = 0; kk < 16; kk++) {
            const int kc = kk * 8;
            uint32_t a0 = H1[(m0 + g) * SH1 + kc + tg];
            uint32_t a1 = H1[(m0 + g + 8) * SH1 + kc + tg];
            uint32_t a2 = H1[(m0 + g) * SH1 + kc + tg + 4];
            uint32_t a3 = H1[(m0 + g + 8) * SH1 + kc + tg + 4];
            const uint2* bp = BW2 + kk * 256 + (q * 2) * 32 + lane;
            #pragma unroll
            for (int l = 0; l < 2; l++) {
                uint2 b = bp[l * 32];
                mma_tf32(acc2[l], a0, a1, a2, a3, b.x, b.y);
            }
        }
        #pragma unroll
        for (int l = 0; l < 2; l++) {
            int col = (q * 2 + l) * 8 + 2 * tg;
            float ba = b2s[col], bb = b2s[col + 1];
            uint2 u0, u1;
            u0.x = f2tf32(silu(acc2[l][0] + ba));
            u0.y = f2tf32(silu(acc2[l][1] + bb));
            u1.x = f2tf32(silu(acc2[l][2] + ba));
            u1.y = f2tf32(silu(acc2[l][3] + bb));
            *(uint2*)&A1[h2base + g * SH2 + col]       = u0;
            *(uint2*)&A1[h2base + (g + 8) * SH2 + col] = u1;
        }
        BAR_STRIPE(barid);

        // ================= L3: [16x64] @ W3 -> 16x8 (1 nt) ==================
        float acc3[4];
        #pragma unroll
        for (int p = 0; p < 4; p++) acc3[p] = 0.0f;

        #pragma unroll
        for (int kk = 0; kk < 8; kk++) {
            const int kc = kk * 8;
            uint32_t a0 = A1[h2base + g * SH2 + kc + tg];
            uint32_t a1 = A1[h2base + (g + 8) * SH2 + kc + tg];
            uint32_t a2 = A1[h2base + g * SH2 + kc + tg + 4];
            uint32_t a3 = A1[h2base + (g + 8) * SH2 + kc + tg + 4];
            uint2 b = BW3[kk * 128 + q * 32 + lane];
            mma_tf32(acc3, a0, a1, a2, a3, b.x, b.y);
        }

        // ---- epi3: partial dot over this warp's 8 cols ----
        {
            int col = q * 8 + 2 * tg;
            float ba = b3s[col], bb = b3s[col + 1];
            float wa = W4s[col], wb = W4s[col + 1];
            float s0 = fmaf(silu(acc3[0] + ba), wa, silu(acc3[1] + bb) * wb);
            float s1 = fmaf(silu(acc3[2] + ba), wa, silu(acc3[3] + bb) * wb);
            s0 += __shfl_xor_sync(0xffffffff, s0, 1);
            s0 += __shfl_xor_sync(0xffffffff, s0, 2);
            s1 += __shfl_xor_sync(0xffffffff, s1, 1);
            s1 += __shfl_xor_sync(0xffffffff, s1, 2);
            if (tg == 0) {
                P4[(m0 + g) * 4 + q]     = s0;
                P4[(m0 + g + 8) * 4 + q] = s1;
            }
        }
        BAR_STRIPE(barid);

        if (q == 0 && lane < 16) {
            float4 p = *(float4*)&P4[(m0 + lane) * 4];
            raw_out[(row0 + m0 + lane) * NC + c] = p.x + p.y + p.z + p.w + b4c;
        }
        BAR_STRIPE(barid);   // raw/P4 read done; A1 stripe free for next tile
    }
}

__global__ __launch_bounds__(256) void couple_kernel(
    const float* __restrict__ raw, float* __restrict__ act,
    const float* __restrict__ coupling, const float* __restrict__ decay)
{
    __shared__ float M[NC][NC];
    if (threadIdx.x < NC * NC) {
        int cp = threadIdx.x / NC;
        int cc = threadIdx.x % NC;
        M[cp][cc] = decay[cp] * coupling[cp * NC + cc] * CF_K;
    }
    __syncthreads();

    int r = blockIdx.x * blockDim.x + threadIdx.x;
    if (r >= NB) return;

    float rw[NC], a[NC];
    #pragma unroll
    for (int c = 0; c < NC; c++) {
        rw[c] = raw[(size_t)r * NC + c];
        a[c]  = sigm(rw[c]);
    }
    #pragma unroll
    for (int it = 0; it < 5; it++) {
        float d[NC];
        #pragma unroll
        for (int c = 0; c < NC; c++) d[c] = 0.0f;
        #pragma unroll
        for (int cp = 0; cp < NC; cp++)
            #pragma unroll
            for (int cc = 0; cc < NC; cc++)
                d[cc] = fmaf(a[cp], M[cp][cc], d[cc]);
        #pragma unroll
        for (int c = 0; c < NC; c++) a[c] = sigm(rw[c] + d[c]);
    }
    #pragma unroll
    for (int c = 0; c < NC; c++) act[(size_t)r * NC + c] = a[c];
}

extern "C" void kernel_launch(void* const* d_in, const int* in_sizes, int n_in,
                              void* d_out, int out_size)
{
    (void)in_sizes; (void)n_in; (void)out_size;
    const float* res      = (const float*)d_in[0];
    const float* W1       = (const float*)d_in[1];
    const float* b1       = (const float*)d_in[2];
    const float* W2       = (const float*)d_in[3];
    const float* b2       = (const float*)d_in[4];
    const float* W3       = (const float*)d_in[5];
    const float* b3       = (const float*)d_in[6];
    const float* W4       = (const float*)d_in[7];
    const float* b4       = (const float*)d_in[8];
    const float* coupling = (const float*)d_in[9];
    const float* decay    = (const float*)d_in[10];

    float* act = (float*)d_out;             // (B, 6)
    float* raw = act + (size_t)NB * NC;     // (B, 6)

    cudaFuncSetAttribute(mlp_mma_kernel, cudaFuncAttributeMaxDynamicSharedMemorySize, SMEM_BYTES);

    mlp_mma_kernel<<<GRID_X, NT, SMEM_BYTES>>>(res, W1, b1, W2, b2, W3, b3, W4, b4, raw);
    couple_kernel<<<NB / 256, 256>>>(raw, act, coupling, decay);
}

// round 13
// speedup vs baseline: 6.0141x; 1.6647x over previous
#include <cuda_runtime.h>
#include <cuda_fp16.h>
#include <cstdint>

#define NB 131072
#define NC 6
#define TILE 128
#define NT 1024
#define CF_K 0.02f
#define T_PER_CTA 4
#define GRID_X (256 * NC)

// activation strides in u32 (half2) units — all ≡ {4,12,20,28} mod 32 for
// conflict-free g*S+tg fragment addressing
#define SA1 60     // 120 halves (K padded 100->112, rest zero)
#define SH1 68     // 136 halves (128 used)
#define SH2 36     // 72 halves (64 used)

// smem byte offsets
#define OFF_A1  0                        // 128 x 60 u32 (res; H2 overlaid per-stripe)   30720
#define OFF_H1  30720                    // 128 x 68 u32                                  34816
#define OFF_BW1 65536                    // 7kk x 16nt x 32 x uint2                       28672
#define OFF_BW2 94208                    // 8kk x 8nt  x 32 x uint2                       16384
#define OFF_BW3 110592                   // 4kk x 4nt  x 32 x uint2                        4096
#define OFF_B1  114688                   // 128 f32
#define OFF_B2  115200                   // 64 f32
#define OFF_B3  115456                   // 32 f32
#define OFF_W4  115584                   // 32 f32
#define OFF_P   115712                   // 128 x 4 f32
#define SMEM_BYTES 117760

__device__ __forceinline__ uint32_t pack_h2(float a, float b) {
    __half2 h = __floats2half2_rn(a, b);
    return *(uint32_t*)&h;
}

__device__ __forceinline__ void mma_f16(float* d,
    uint32_t a0, uint32_t a1, uint32_t a2, uint32_t a3,
    uint32_t b0, uint32_t b1)
{
    asm volatile(
        "mma.sync.aligned.m16n8k16.row.col.f32.f16.f16.f32 "
        "{%0,%1,%2,%3}, {%4,%5,%6,%7}, {%8,%9}, {%0,%1,%2,%3};"
        : "+f"(d[0]), "+f"(d[1]), "+f"(d[2]), "+f"(d[3])
        : "r"(a0), "r"(a1), "r"(a2), "r"(a3), "r"(b0), "r"(b1));
}

__device__ __forceinline__ float sigm(float x) { return 1.0f / (1.0f + __expf(-x)); }
// silu(x) = 0.5x + 0.5x*tanh(x/2)  (1 MUFU)
__device__ __forceinline__ float silu(float x) {
    float t;
    asm("tanh.approx.f32 %0, %1;" : "=f"(t) : "f"(0.5f * x));
    float hx = 0.5f * x;
    return fmaf(hx, t, hx);
}

// per-stripe barrier: 4 warps (128 threads), HW barrier id = stripe+1
#define BAR_STRIPE(id) asm volatile("bar.sync %0, 128;" :: "r"(id) : "memory")

__global__ __launch_bounds__(NT, 1) void mlp_mma_kernel(
    const float* __restrict__ res,
    const float* __restrict__ W1, const float* __restrict__ b1,
    const float* __restrict__ W2, const float* __restrict__ b2,
    const float* __restrict__ W3, const float* __restrict__ b3,
    const float* __restrict__ W4, const float* __restrict__ b4,
    float* __restrict__ raw_out)
{
    extern __shared__ char smb[];
    uint32_t* A1  = (uint32_t*)(smb + OFF_A1);
    uint32_t* H1  = (uint32_t*)(smb + OFF_H1);
    float*    b1s = (float*)(smb + OFF_B1);
    float*    b2s = (float*)(smb + OFF_B2);
    float*    b3s = (float*)(smb + OFF_B3);
    float*    W4s = (float*)(smb + OFF_W4);
    float*    P4  = (float*)(smb + OFF_P);    // [128][4]

    const int bid   = blockIdx.x;
    const int c     = bid % NC;
    const int tbase = bid / NC;

    const int tid    = threadIdx.x;
    const int w      = tid >> 5;
    const int lane   = tid & 31;
    const int g      = lane >> 2;
    const int tg     = lane & 3;
    const int stripe = w >> 2;       // 0..7: 16-row stripe
    const int q      = w & 3;        // 0..3: N quarter
    const int m0     = stripe * 16;
    const int barid  = stripe + 1;
    const int sg_tid = tid & 127;

    // ---- one-time: permute weights to fp16 per-lane fragment order ----
    {
        const float* w1 = W1 + (size_t)c * 100 * 128;
        for (int idx = tid; idx < 7 * 16 * 32; idx += NT) {
            int kk = idx >> 9, rem = idx & 511;
            int nt = rem >> 5, ln = rem & 31;
            int gg = ln >> 2, tt = ln & 3;
            int n = nt * 8 + gg, k0 = kk * 16 + 2 * tt;
            float v0 = (k0     < 100) ? w1[k0 * 128 + n]       : 0.0f;
            float v1 = (k0 + 1 < 100) ? w1[(k0 + 1) * 128 + n] : 0.0f;
            float v2 = (k0 + 8 < 100) ? w1[(k0 + 8) * 128 + n] : 0.0f;
            float v3 = (k0 + 9 < 100) ? w1[(k0 + 9) * 128 + n] : 0.0f;
            uint2 u; u.x = pack_h2(v0, v1); u.y = pack_h2(v2, v3);
            *(uint2*)(smb + OFF_BW1 + (size_t)idx * 8) = u;
        }
        const float* w2 = W2 + (size_t)c * 128 * 64;
        for (int idx = tid; idx < 8 * 8 * 32; idx += NT) {
            int kk = idx >> 8, rem = idx & 255;
            int nt = rem >> 5, ln = rem & 31;
            int gg = ln >> 2, tt = ln & 3;
            int n = nt * 8 + gg, k0 = kk * 16 + 2 * tt;
            uint2 u;
            u.x = pack_h2(w2[k0 * 64 + n],       w2[(k0 + 1) * 64 + n]);
            u.y = pack_h2(w2[(k0 + 8) * 64 + n], w2[(k0 + 9) * 64 + n]);
            *(uint2*)(smb + OFF_BW2 + (size_t)idx * 8) = u;
        }
        const float* w3 = W3 + (size_t)c * 64 * 32;
        for (int idx = tid; idx < 4 * 4 * 32; idx += NT) {
            int kk = idx >> 7, rem = idx & 127;
            int nt = rem >> 5, ln = rem & 31;
            int gg = ln >> 2, tt = ln & 3;
            int n = nt * 8 + gg, k0 = kk * 16 + 2 * tt;
            uint2 u;
            u.x = pack_h2(w3[k0 * 32 + n],       w3[(k0 + 1) * 32 + n]);
            u.y = pack_h2(w3[(k0 + 8) * 32 + n], w3[(k0 + 9) * 32 + n]);
            *(uint2*)(smb + OFF_BW3 + (size_t)idx * 8) = u;
        }
        if (tid < 128) b1s[tid] = b1[c * 128 + tid];
        if (tid < 64)  b2s[tid] = b2[c * 64 + tid];
        if (tid < 32)  b3s[tid] = b3[c * 32 + tid];
        if (tid < 32)  W4s[tid] = W4[c * 32 + tid];
    }
    const float b4c = b4[c];
    __syncthreads();

    const uint2* BW1 = (const uint2*)(smb + OFF_BW1);
    const uint2* BW2 = (const uint2*)(smb + OFF_BW2);

    // hoist L3 B fragments (constant across tiles): 4 kk, this warp's nt = q
    uint2 bw3[4];
    {
        const uint2* BW3 = (const uint2*)(smb + OFF_BW3);
        #pragma unroll
        for (int kk = 0; kk < 4; kk++) bw3[kk] = BW3[kk * 128 + q * 32 + lane];
    }

    // H2 overlays A1 stripe-locally: stripe base (u32)
    const int h2b = m0 * SA1;

    for (int j = 0; j < T_PER_CTA; j++) {
        const size_t row0 = (size_t)(tbase + 256 * j) * TILE;

        // ---- load this stripe's 16 res rows as half2 (zero-pad K to 120) ----
        {
            const float* rp = res + (row0 + m0) * 100;
            #pragma unroll
            for (int i = 0; i < 8; i++) {
                int idx = sg_tid + i * 128;       // 0..959 (16 rows x 60 u32)
                if (i == 7 && idx >= 960) break;
                int rr = idx / SA1, k2 = idx - rr * SA1;
                int k = 2 * k2;
                float f0 = (k     < 100) ? rp[rr * 100 + k]     : 0.0f;
                float f1 = (k + 1 < 100) ? rp[rr * 100 + k + 1] : 0.0f;
                A1[(m0 + rr) * SA1 + k2] = pack_h2(f0, f1);
            }
        }
        BAR_STRIPE(barid);

        // ================= L1: [16x112] @ W1 -> 16x32 (4 nt, 7 kk) ==========
        float acc1[4][4];
        #pragma unroll
        for (int l = 0; l < 4; l++)
            #pragma unroll
            for (int p = 0; p < 4; p++) acc1[l][p] = 0.0f;

        #pragma unroll
        for (int kk = 0; kk < 7; kk++) {
            const int kc2 = kk * 8;
            uint32_t a0 = A1[(m0 + g) * SA1 + kc2 + tg];
            uint32_t a1 = A1[(m0 + g + 8) * SA1 + kc2 + tg];
            uint32_t a2 = A1[(m0 + g) * SA1 + kc2 + 4 + tg];
            uint32_t a3 = A1[(m0 + g + 8) * SA1 + kc2 + 4 + tg];
            const uint2* bp = BW1 + kk * 512 + (q * 4) * 32 + lane;
            #pragma unroll
            for (int l = 0; l < 4; l++) {
                uint2 b = bp[l * 32];
                mma_f16(acc1[l], a0, a1, a2, a3, b.x, b.y);
            }
        }
        #pragma unroll
        for (int l = 0; l < 4; l++) {
            int col = (q * 4 + l) * 8 + 2 * tg;
            float ba = b1s[col], bb = b1s[col + 1];
            int p2 = (q * 4 + l) * 4 + tg;
            H1[(m0 + g) * SH1 + p2]     = pack_h2(silu(acc1[l][0] + ba), silu(acc1[l][1] + bb));
            H1[(m0 + g + 8) * SH1 + p2] = pack_h2(silu(acc1[l][2] + ba), silu(acc1[l][3] + bb));
        }
        BAR_STRIPE(barid);

        // ================= L2: [16x128] @ W2 -> 16x16 (2 nt, 8 kk) ==========
        float acc2[2][4];
        #pragma unroll
        for (int l = 0; l < 2; l++)
            #pragma unroll
            for (int p = 0; p < 4; p++) acc2[l][p] = 0.0f;

        #pragma unroll
        for (int kk = 0; kk < 8; kk++) {
            const int kc2 = kk * 8;
            uint32_t a0 = H1[(m0 + g) * SH1 + kc2 + tg];
            uint32_t a1 = H1[(m0 + g + 8) * SH1 + kc2 + tg];
            uint32_t a2 = H1[(m0 + g) * SH1 + kc2 + 4 + tg];
            uint32_t a3 = H1[(m0 + g + 8) * SH1 + kc2 + 4 + tg];
            const uint2* bp = BW2 + kk * 256 + (q * 2) * 32 + lane;
            #pragma unroll
            for (int l = 0; l < 2; l++) {
                uint2 b = bp[l * 32];
                mma_f16(acc2[l], a0, a1, a2, a3, b.x, b.y);
            }
        }
        #pragma unroll
        for (int l = 0; l < 2; l++) {
            int col = (q * 2 + l) * 8 + 2 * tg;
            float ba = b2s[col], bb = b2s[col + 1];
            int p2 = (q * 2 + l) * 4 + tg;
            A1[h2b + g * SH2 + p2]       = pack_h2(silu(acc2[l][0] + ba), silu(acc2[l][1] + bb));
            A1[h2b + (g + 8) * SH2 + p2] = pack_h2(silu(acc2[l][2] + ba), silu(acc2[l][3] + bb));
        }
        BAR_STRIPE(barid);

        // ================= L3: [16x64] @ W3 -> 16x8 (1 nt, 4 kk) ============
        float acc3[4];
        #pragma unroll
        for (int p = 0; p < 4; p++) acc3[p] = 0.0f;

        #pragma unroll
        for (int kk = 0; kk < 4; kk++) {
            const int kc2 = kk * 8;
            uint32_t a0 = A1[h2b + g * SH2 + kc2 + tg];
            uint32_t a1 = A1[h2b + (g + 8) * SH2 + kc2 + tg];
            uint32_t a2 = A1[h2b + g * SH2 + kc2 + 4 + tg];
            uint32_t a3 = A1[h2b + (g + 8) * SH2 + kc2 + 4 + tg];
            mma_f16(acc3, a0, a1, a2, a3, bw3[kk].x, bw3[kk].y);
        }

        // ---- epi3: partial dot over this warp's 8 cols ----
        {
            int col = q * 8 + 2 * tg;
            float ba = b3s[col], bb = b3s[col + 1];
            float wa = W4s[col], wb = W4s[col + 1];
            float s0 = fmaf(silu(acc3[0] + ba), wa, silu(acc3[1] + bb) * wb);
            float s1 = fmaf(silu(acc3[2] + ba), wa, silu(acc3[3] + bb) * wb);
            s0 += __shfl_xor_sync(0xffffffff, s0, 1);
            s0 += __shfl_xor_sync(0xffffffff, s0, 2);
            s1 += __shfl_xor_sync(0xffffffff, s1, 1);
            s1 += __shfl_xor_sync(0xffffffff, s1, 2);
            if (tg == 0) {
                P4[(m0 + g) * 4 + q]     = s0;
                P4[(m0 + g + 8) * 4 + q] = s1;
            }
        }
        BAR_STRIPE(barid);

        if (q == 0 && lane < 16) {
            float4 p = *(float4*)&P4[(m0 + lane) * 4];
            raw_out[(row0 + m0 + lane) * NC + c] = p.x + p.y + p.z + p.w + b4c;
        }
        BAR_STRIPE(barid);   // stripe fully drained; A1/H2 region reusable
    }
}

__global__ __launch_bounds__(256) void couple_kernel(
    const float* __restrict__ raw, float* __restrict__ act,
    const float* __restrict__ coupling, const float* __restrict__ decay)
{
    __shared__ float M[NC][NC];
    if (threadIdx.x < NC * NC) {
        int cp = threadIdx.x / NC;
        int cc = threadIdx.x % NC;
        M[cp][cc] = decay[cp] * coupling[cp * NC + cc] * CF_K;
    }
    __syncthreads();

    int r = blockIdx.x * blockDim.x + threadIdx.x;
    if (r >= NB) return;

    float rw[NC], a[NC];
    #pragma unroll
    for (int c = 0; c < NC; c++) {
        rw[c] = raw[(size_t)r * NC + c];
        a[c]  = sigm(rw[c]);
    }
    #pragma unroll
    for (int it = 0; it < 5; it++) {
        float d[NC];
        #pragma unroll
        for (int c = 0; c < NC; c++) d[c] = 0.0f;
        #pragma unroll
        for (int cp = 0; cp < NC; cp++)
            #pragma unroll
            for (int cc = 0; cc < NC; cc++)
                d[cc] = fmaf(a[cp], M[cp][cc], d[cc]);
        #pragma unroll
        for (int c = 0; c < NC; c++) a[c] = sigm(rw[c] + d[c]);
    }
    #pragma unroll
    for (int c = 0; c < NC; c++) act[(size_t)r * NC + c] = a[c];
}

extern "C" void kernel_launch(void* const* d_in, const int* in_sizes, int n_in,
                              void* d_out, int out_size)
{
    (void)in_sizes; (void)n_in; (void)out_size;
    const float* res      = (const float*)d_in[0];
    const float* W1       = (const float*)d_in[1];
    const float* b1       = (const float*)d_in[2];
    const float* W2       = (const float*)d_in[3];
    const float* b2       = (const float*)d_in[4];
    const float* W3       = (const float*)d_in[5];
    const float* b3       = (const float*)d_in[6];
    const float* W4       = (const float*)d_in[7];
    const float* b4       = (const float*)d_in[8];
    const float* coupling = (const float*)d_in[9];
    const float* decay    = (const float*)d_in[10];

    float* act = (float*)d_out;             // (B, 6)
    float* raw = act + (size_t)NB * NC;     // (B, 6)

    cudaFuncSetAttribute(mlp_mma_kernel, cudaFuncAttributeMaxDynamicSharedMemorySize, SMEM_BYTES);

    mlp_mma_kernel<<<GRID_X, NT, SMEM_BYTES>>>(res, W1, b1, W2, b2, W3, b3, W4, b4, raw);
    couple_kernel<<<NB / 256, 256>>>(raw, act, coupling, decay);
}

// round 14
// speedup vs baseline: 6.7986x; 1.1304x over previous
#include <cuda_runtime.h>
#include <cuda_fp16.h>
#include <cstdint>

#define NB 131072
#define NC 6
#define TILE 128
#define NT 1024
#define CF_K 0.02f
#define T_PER_CTA 4
#define GRID_X (256 * NC)

// strides in u32 (half2) units — ≡4 mod 32 (or 28/20/12) => conflict-free frags
#define SA1 60     // 120 halves (K padded 100->112)
#define SH1 68     // 136 halves (128 used)
#define SH2 36     // 72 halves (64 used)

// smem byte offsets (two tile-groups for A1/H1/P4)
#define OFF_A1  0                        // 2 x 128 x 60 u32      61440
#define OFF_H1  61440                    // 2 x 128 x 68 u32      69632
#define OFF_BW1 131072                   // 7kk x 16nt x 32 x uint2  28672
#define OFF_BW2 159744                   // 8kk x 8nt  x 32 x uint2  16384
#define OFF_BW3 176128                   // 4kk x 4nt  x 32 x uint2   4096
#define OFF_B1  180224                   // 128 f32
#define OFF_B2  180736                   // 64 f32
#define OFF_B3  180992                   // 32 f32
#define OFF_W4  181120                   // 32 f32
#define OFF_P   181248                   // 2 x 128 x 4 f32  4096
#define SMEM_BYTES 185344

// fp16 copy of res, written once per launch by conv_kernel (26 MB scratch)
__device__ uint32_t g_res_h2[NB * 50];

__device__ __forceinline__ uint32_t pack_h2(float a, float b) {
    __half2 h = __floats2half2_rn(a, b);
    return *(uint32_t*)&h;
}

__device__ __forceinline__ void mma_f16(float* d,
    uint32_t a0, uint32_t a1, uint32_t a2, uint32_t a3,
    uint32_t b0, uint32_t b1)
{
    asm volatile(
        "mma.sync.aligned.m16n8k16.row.col.f32.f16.f16.f32 "
        "{%0,%1,%2,%3}, {%4,%5,%6,%7}, {%8,%9}, {%0,%1,%2,%3};"
        : "+f"(d[0]), "+f"(d[1]), "+f"(d[2]), "+f"(d[3])
        : "r"(a0), "r"(a1), "r"(a2), "r"(a3), "r"(b0), "r"(b1));
}

// sigmoid(x) = 0.5*tanh(x/2) + 0.5   (1 MUFU)
__device__ __forceinline__ float sigm(float x) {
    float t;
    asm("tanh.approx.f32 %0, %1;" : "=f"(t) : "f"(0.5f * x));
    return fmaf(0.5f, t, 0.5f);
}
// silu(x) = 0.5x + 0.5x*tanh(x/2)   (1 MUFU)
__device__ __forceinline__ float silu(float x) {
    float t;
    asm("tanh.approx.f32 %0, %1;" : "=f"(t) : "f"(0.5f * x));
    float hx = 0.5f * x;
    return fmaf(hx, t, hx);
}

#define BAR_GRP(id) asm volatile("bar.sync %0, 128;" :: "r"(id) : "memory")

__global__ __launch_bounds__(512) void conv_kernel(const float* __restrict__ res) {
    int i = blockIdx.x * blockDim.x + threadIdx.x;   // < NB*25
    float4 f = ((const float4*)res)[i];
    uint2 u;
    u.x = pack_h2(f.x, f.y);
    u.y = pack_h2(f.z, f.w);
    ((uint2*)g_res_h2)[i] = u;
}

__global__ __launch_bounds__(NT, 1) void mlp_mma_kernel(
    const float* __restrict__ W1, const float* __restrict__ b1,
    const float* __restrict__ W2, const float* __restrict__ b2,
    const float* __restrict__ W3, const float* __restrict__ b3,
    const float* __restrict__ W4, const float* __restrict__ b4,
    float* __restrict__ raw_out)
{
    extern __shared__ char smb[];
    float* b1s = (float*)(smb + OFF_B1);
    float* b2s = (float*)(smb + OFF_B2);
    float* b3s = (float*)(smb + OFF_B3);
    float* W4s = (float*)(smb + OFF_W4);

    const int bid   = blockIdx.x;
    const int c     = bid % NC;
    const int tbase = bid / NC;

    const int tid  = threadIdx.x;
    const int w    = tid >> 5;
    const int lane = tid & 31;
    const int g    = lane >> 2;
    const int tg   = lane & 3;
    const int G    = w >> 4;          // tile-group 0/1
    const int bs   = (w >> 2) & 3;    // big-stripe (32 rows)
    const int q    = w & 3;           // N quarter
    const int m0   = bs * 32;
    const int barid = 1 + G * 4 + bs;
    const int sg128 = tid & 127;

    uint32_t* A1g = (uint32_t*)(smb + OFF_A1) + G * (128 * SA1);
    uint32_t* H1g = (uint32_t*)(smb + OFF_H1) + G * (128 * SH1);
    float*    P4g = (float*)(smb + OFF_P) + G * 512;

    // ---- one-time: permute weights to fp16 per-lane fragment order ----
    {
        const float* w1 = W1 + (size_t)c * 100 * 128;
        for (int idx = tid; idx < 7 * 16 * 32; idx += NT) {
            int kk = idx >> 9, rem = idx & 511;
            int nt = rem >> 5, ln = rem & 31;
            int gg = ln >> 2, tt = ln & 3;
            int n = nt * 8 + gg, k0 = kk * 16 + 2 * tt;
            float v0 = (k0     < 100) ? w1[k0 * 128 + n]       : 0.0f;
            float v1 = (k0 + 1 < 100) ? w1[(k0 + 1) * 128 + n] : 0.0f;
            float v2 = (k0 + 8 < 100) ? w1[(k0 + 8) * 128 + n] : 0.0f;
            float v3 = (k0 + 9 < 100) ? w1[(k0 + 9) * 128 + n] : 0.0f;
            uint2 u; u.x = pack_h2(v0, v1); u.y = pack_h2(v2, v3);
            *(uint2*)(smb + OFF_BW1 + (size_t)idx * 8) = u;
        }
        const float* w2 = W2 + (size_t)c * 128 * 64;
        for (int idx = tid; idx < 8 * 8 * 32; idx += NT) {
            int kk = idx >> 8, rem = idx & 255;
            int nt = rem >> 5, ln = rem & 31;
            int gg = ln >> 2, tt = ln & 3;
            int n = nt * 8 + gg, k0 = kk * 16 + 2 * tt;
            uint2 u;
            u.x = pack_h2(w2[k0 * 64 + n],       w2[(k0 + 1) * 64 + n]);
            u.y = pack_h2(w2[(k0 + 8) * 64 + n], w2[(k0 + 9) * 64 + n]);
            *(uint2*)(smb + OFF_BW2 + (size_t)idx * 8) = u;
        }
        const float* w3 = W3 + (size_t)c * 64 * 32;
        for (int idx = tid; idx < 4 * 4 * 32; idx += NT) {
            int kk = idx >> 7, rem = idx & 127;
            int nt = rem >> 5, ln = rem & 31;
            int gg = ln >> 2, tt = ln & 3;
            int n = nt * 8 + gg, k0 = kk * 16 + 2 * tt;
            uint2 u;
            u.x = pack_h2(w3[k0 * 32 + n],       w3[(k0 + 1) * 32 + n]);
            u.y = pack_h2(w3[(k0 + 8) * 32 + n], w3[(k0 + 9) * 32 + n]);
            *(uint2*)(smb + OFF_BW3 + (size_t)idx * 8) = u;
        }
        if (tid < 128) b1s[tid] = b1[c * 128 + tid];
        if (tid < 64)  b2s[tid] = b2[c * 64 + tid];
        if (tid < 32)  b3s[tid] = b3[c * 32 + tid];
        if (tid < 32)  W4s[tid] = W4[c * 32 + tid];
    }
    const float b4c = b4[c];
    __syncthreads();

    const uint2* BW1 = (const uint2*)(smb + OFF_BW1);
    const uint2* BW2 = (const uint2*)(smb + OFF_BW2);

    // hoist L3 B fragments (constant): 4 kk, this warp's nt = q
    uint2 bw3[4];
    {
        const uint2* BW3 = (const uint2*)(smb + OFF_BW3);
        #pragma unroll
        for (int kk = 0; kk < 4; kk++) bw3[kk] = BW3[kk * 128 + q * 32 + lane];
    }

    const int h2b = m0 * SA1;   // H2 overlay base inside this group/stripe of A1

    #pragma unroll
    for (int it = 0; it < 2; it++) {
        const int j = 2 * it + G;
        const size_t row0 = (size_t)(tbase + 256 * j) * TILE;

        // ---- load this big-stripe's 32 res rows (fp16, pad K to 120) ----
        {
            const uint32_t* rp = g_res_h2 + (row0 + m0) * 50;
            #pragma unroll
            for (int i = 0; i < 15; i++) {
                int idx = sg128 + i * 128;         // 0..1919
                int rr = idx / SA1, k2 = idx - rr * SA1;
                A1g[(m0 + rr) * SA1 + k2] = (k2 < 50) ? rp[rr * 50 + k2] : 0u;
            }
        }
        BAR_GRP(barid);

        // ============ L1: [32x112] @ W1 -> 32x32 (4 nt x 2 mh, 7 kk) ========
        float acc1[4][2][4];
        #pragma unroll
        for (int l = 0; l < 4; l++)
            #pragma unroll
            for (int mh = 0; mh < 2; mh++)
                #pragma unroll
                for (int p = 0; p < 4; p++) acc1[l][mh][p] = 0.0f;

        #pragma unroll
        for (int kk = 0; kk < 7; kk++) {
            const int kc2 = kk * 8;
            uint32_t a[2][4];
            #pragma unroll
            for (int mh = 0; mh < 2; mh++) {
                int rb = m0 + mh * 16;
                a[mh][0] = A1g[(rb + g) * SA1 + kc2 + tg];
                a[mh][1] = A1g[(rb + g + 8) * SA1 + kc2 + tg];
                a[mh][2] = A1g[(rb + g) * SA1 + kc2 + 4 + tg];
                a[mh][3] = A1g[(rb + g + 8) * SA1 + kc2 + 4 + tg];
            }
            const uint2* bp = BW1 + kk * 512 + (q * 4) * 32 + lane;
            #pragma unroll
            for (int l = 0; l < 4; l++) {
                uint2 b = bp[l * 32];
                mma_f16(acc1[l][0], a[0][0], a[0][1], a[0][2], a[0][3], b.x, b.y);
                mma_f16(acc1[l][1], a[1][0], a[1][1], a[1][2], a[1][3], b.x, b.y);
            }
        }
        #pragma unroll
        for (int l = 0; l < 4; l++) {
            int col = (q * 4 + l) * 8 + 2 * tg;
            float ba = b1s[col], bb = b1s[col + 1];
            int p2 = (q * 4 + l) * 4 + tg;
            #pragma unroll
            for (int mh = 0; mh < 2; mh++) {
                int rb = m0 + mh * 16;
                H1g[(rb + g) * SH1 + p2]     = pack_h2(silu(acc1[l][mh][0] + ba), silu(acc1[l][mh][1] + bb));
                H1g[(rb + g + 8) * SH1 + p2] = pack_h2(silu(acc1[l][mh][2] + ba), silu(acc1[l][mh][3] + bb));
            }
        }
        BAR_GRP(barid);

        // ============ L2: [32x128] @ W2 -> 32x16 (2 nt x 2 mh, 8 kk) ========
        float acc2[2][2][4];
        #pragma unroll
        for (int l = 0; l < 2; l++)
            #pragma unroll
            for (int mh = 0; mh < 2; mh++)
                #pragma unroll
                for (int p = 0; p < 4; p++) acc2[l][mh][p] = 0.0f;

        #pragma unroll
        for (int kk = 0; kk < 8; kk++) {
            const int kc2 = kk * 8;
            uint32_t a[2][4];
            #pragma unroll
            for (int mh = 0; mh < 2; mh++) {
                int rb = m0 + mh * 16;
                a[mh][0] = H1g[(rb + g) * SH1 + kc2 + tg];
                a[mh][1] = H1g[(rb + g + 8) * SH1 + kc2 + tg];
                a[mh][2] = H1g[(rb + g) * SH1 + kc2 + 4 + tg];
                a[mh][3] = H1g[(rb + g + 8) * SH1 + kc2 + 4 + tg];
            }
            const uint2* bp = BW2 + kk * 256 + (q * 2) * 32 + lane;
            #pragma unroll
            for (int l = 0; l < 2; l++) {
                uint2 b = bp[l * 32];
                mma_f16(acc2[l][0], a[0][0], a[0][1], a[0][2], a[0][3], b.x, b.y);
                mma_f16(acc2[l][1], a[1][0], a[1][1], a[1][2], a[1][3], b.x, b.y);
            }
        }
        #pragma unroll
        for (int l = 0; l < 2; l++) {
            int col = (q * 2 + l) * 8 + 2 * tg;
            float ba = b2s[col], bb = b2s[col + 1];
            int p2 = (q * 2 + l) * 4 + tg;
            #pragma unroll
            for (int mh = 0; mh < 2; mh++) {
                int r2 = mh * 16;
                A1g[h2b + (r2 + g) * SH2 + p2]     = pack_h2(silu(acc2[l][mh][0] + ba), silu(acc2[l][mh][1] + bb));
                A1g[h2b + (r2 + g + 8) * SH2 + p2] = pack_h2(silu(acc2[l][mh][2] + ba), silu(acc2[l][mh][3] + bb));
            }
        }
        BAR_GRP(barid);

        // ============ L3: [32x64] @ W3 -> 32x8 (1 nt x 2 mh, 4 kk) ==========
        float acc3[2][4];
        #pragma unroll
        for (int mh = 0; mh < 2; mh++)
            #pragma unroll
            for (int p = 0; p < 4; p++) acc3[mh][p] = 0.0f;

        #pragma unroll
        for (int kk = 0; kk < 4; kk++) {
            const int kc2 = kk * 8;
            #pragma unroll
            for (int mh = 0; mh < 2; mh++) {
                int r2 = mh * 16;
                uint32_t a0 = A1g[h2b + (r2 + g) * SH2 + kc2 + tg];
                uint32_t a1 = A1g[h2b + (r2 + g + 8) * SH2 + kc2 + tg];
                uint32_t a2 = A1g[h2b + (r2 + g) * SH2 + kc2 + 4 + tg];
                uint32_t a3 = A1g[h2b + (r2 + g + 8) * SH2 + kc2 + 4 + tg];
                mma_f16(acc3[mh], a0, a1, a2, a3, bw3[kk].x, bw3[kk].y);
            }
        }

        // ---- epi3: partial dot over this warp's 8 cols ----
        {
            int col = q * 8 + 2 * tg;
            float ba = b3s[col], bb = b3s[col + 1];
            float wa = W4s[col], wb = W4s[col + 1];
            #pragma unroll
            for (int mh = 0; mh < 2; mh++) {
                float s0 = fmaf(silu(acc3[mh][0] + ba), wa, silu(acc3[mh][1] + bb) * wb);
                float s1 = fmaf(silu(acc3[mh][2] + ba), wa, silu(acc3[mh][3] + bb) * wb);
                s0 += __shfl_xor_sync(0xffffffff, s0, 1);
                s0 += __shfl_xor_sync(0xffffffff, s0, 2);
                s1 += __shfl_xor_sync(0xffffffff, s1, 1);
                s1 += __shfl_xor_sync(0xffffffff, s1, 2);
                if (tg == 0) {
                    P4g[(m0 + mh * 16 + g) * 4 + q]     = s0;
                    P4g[(m0 + mh * 16 + g + 8) * 4 + q] = s1;
                }
            }
        }
        BAR_GRP(barid);

        if (q == 0) {
            float4 p = *(float4*)&P4g[(m0 + lane) * 4];
            raw_out[(row0 + m0 + lane) * NC + c] = p.x + p.y + p.z + p.w + b4c;
        }
        BAR_GRP(barid);   // stripe drained; A1/P4 reusable next iteration
    }
}

__global__ __launch_bounds__(256) void couple_kernel(
    const float* __restrict__ raw, float* __restrict__ act,
    const float* __restrict__ coupling, const float* __restrict__ decay)
{
    __shared__ float M[NC][NC];
    if (threadIdx.x < NC * NC) {
        int cp = threadIdx.x / NC;
        int cc = threadIdx.x % NC;
        M[cp][cc] = decay[cp] * coupling[cp * NC + cc] * CF_K;
    }
    __syncthreads();

    int r = blockIdx.x * blockDim.x + threadIdx.x;
    if (r >= NB) return;

    float rw[NC], a[NC];
    const float2* rp = (const float2*)(raw + (size_t)r * NC);
    #pragma unroll
    for (int h = 0; h < 3; h++) {
        float2 v = rp[h];
        rw[2 * h] = v.x; rw[2 * h + 1] = v.y;
    }
    #pragma unroll
    for (int c = 0; c < NC; c++) a[c] = sigm(rw[c]);

    #pragma unroll
    for (int it = 0; it < 5; it++) {
        float d[NC];
        #pragma unroll
        for (int c = 0; c < NC; c++) d[c] = 0.0f;
        #pragma unroll
        for (int cp = 0; cp < NC; cp++)
            #pragma unroll
            for (int cc = 0; cc < NC; cc++)
                d[cc] = fmaf(a[cp], M[cp][cc], d[cc]);
        #pragma unroll
        for (int c = 0; c < NC; c++) a[c] = sigm(rw[c] + d[c]);
    }
    float2* ap = (float2*)(act + (size_t)r * NC);
    #pragma unroll
    for (int h = 0; h < 3; h++) {
        float2 v; v.x = a[2 * h]; v.y = a[2 * h + 1];
        ap[h] = v;
    }
}

extern "C" void kernel_launch(void* const* d_in, const int* in_sizes, int n_in,
                              void* d_out, int out_size)
{
    (void)in_sizes; (void)n_in; (void)out_size;
    const float* res      = (const float*)d_in[0];
    const float* W1       = (const float*)d_in[1];
    const float* b1       = (const float*)d_in[2];
    const float* W2       = (const float*)d_in[3];
    const float* b2       = (const float*)d_in[4];
    const float* W3       = (const float*)d_in[5];
    const float* b3       = (const float*)d_in[6];
    const float* W4       = (const float*)d_in[7];
    const float* b4       = (const float*)d_in[8];
    const float* coupling = (const float*)d_in[9];
    const float* decay    = (const float*)d_in[10];

    float* act = (float*)d_out;             // (B, 6)
    float* raw = act + (size_t)NB * NC;     // (B, 6)

    cudaFuncSetAttribute(mlp_mma_kernel, cudaFuncAttributeMaxDynamicSharedMemorySize, SMEM_BYTES);

    conv_kernel<<<NB * 25 / 512, 512>>>(res);
    mlp_mma_kernel<<<GRID_X, NT, SMEM_BYTES>>>(W1, b1, W2, b2, W3, b3, W4, b4, raw);
    couple_kernel<<<NB / 256, 256>>>(raw, act, coupling, decay);
}